// round 13
// baseline (speedup 1.0000x reference)
#include <cuda_runtime.h>
#include <cuda_bf16.h>
#include <cstdint>

#define TILE_H 16
#define TILE_W 32
#define HALO_H (TILE_H + 2)        // 18
#define ROWSPAN 40                 // padded row: gmem cols [tw0-4, tw0+36), 160B aligned
#define PLANE  (HALO_H * ROWSPAN)  // 720 floats per channel plane
#define CCH    64
#define HH     128
#define WWD    128
#define HW     (HH * WWD)
#define NTAP   9
#define CHUNK  8
#define NCHUNK (CCH / CHUNK)       // 8
#define NBUF   3
#define NTHREADS 128
#define NPX    4                   // vertical pixels per thread
#define NSLOT4 (CHUNK * HALO_H * 10)   // 1440 float4 slots per chunk staging

#define XS_ELEMS  (CHUNK * PLANE)      // 5760 floats per buffer
#define WSA_ELEMS (NTAP * CCH * 8)     // 4608: k=0..7 pairs, [tap][c][8]
#define WSB_ELEMS (CCH * 12)           // 768:  k=8 weights, [c][tap] padded to 12
#define SMEM_BYTES ((NBUF * XS_ELEMS + WSA_ELEMS + WSB_ELEMS) * 4)  // 90624 B -> 2 CTA/SM

extern __shared__ float smem[];

typedef unsigned long long u64t;

#define CP_COMMIT() asm volatile("cp.async.commit_group;\n" ::: "memory")
#define CP_WAIT0()  asm volatile("cp.async.wait_group 0;\n" ::: "memory")
#define CP_WAIT1()  asm volatile("cp.async.wait_group 1;\n" ::: "memory")

__device__ __forceinline__ u64t pack2(float lo, float hi) {
    u64t r;
    asm("mov.b64 %0, {%1, %2};" : "=l"(r) : "r"(__float_as_uint(lo)), "r"(__float_as_uint(hi)));
    return r;
}
__device__ __forceinline__ u64t dup2(float v) {
    u64t r;
    asm("mov.b64 %0, {%1, %1};" : "=l"(r) : "r"(__float_as_uint(v)));
    return r;
}
// d = a*b + c elementwise on packed f32x2 -> single FFMA2 in SASS
__device__ __forceinline__ u64t ffma2(u64t a, u64t b, u64t c) {
    u64t d;
    asm("fma.rn.f32x2 %0, %1, %2, %3;" : "=l"(d) : "l"(a), "l"(b), "l"(c));
    return d;
}

// One 8-channel chunk = 1440 aligned float4 copies; 12 slots/thread (last partial),
// descriptors precomputed once. Invalid slots zero-fill via cp.async src-size=0,
// which also writes the conv's zero halo at image borders.
__device__ __forceinline__ void stage_async(float* __restrict__ buf,
                                            const float* __restrict__ xc,
                                            const int* __restrict__ goff,
                                            int tid)
{
    uint32_t sa = (uint32_t)__cvta_generic_to_shared(buf) + (uint32_t)tid * 16u;
    #pragma unroll
    for (int s = 0; s < 11; ++s) {
        const int o = goff[s];
        const float* src = xc + (o >= 0 ? o : 0);
        const int z = (o >= 0) ? 16 : 0;
        asm volatile("cp.async.cg.shared.global [%0], [%1], 16, %2;\n"
                     :: "r"(sa + (uint32_t)s * (NTHREADS * 16u)), "l"(src), "r"(z) : "memory");
    }
    if (tid < (NSLOT4 - 11 * NTHREADS)) {   // tid < 32
        const int o = goff[11];
        const float* src = xc + (o >= 0 ? o : 0);
        const int z = (o >= 0) ? 16 : 0;
        asm volatile("cp.async.cg.shared.global [%0], [%1], 16, %2;\n"
                     :: "r"(sa + 11u * (NTHREADS * 16u)), "l"(src), "r"(z) : "memory");
    }
}

__global__ __launch_bounds__(NTHREADS, 4)
void ahpf_fused_kernel(const float* __restrict__ x,
                       const float* __restrict__ Wt,
                       const float* __restrict__ bias,
                       float* __restrict__ out)
{
    float* xb0 = smem;
    float* xb1 = smem + XS_ELEMS;
    float* xb2 = smem + 2 * XS_ELEMS;
    float* wsA = smem + NBUF * XS_ELEMS;            // [tap][c][8] : k=0..7
    float* wsB = wsA + WSA_ELEMS;                   // [c][12]     : k=8 per tap
    float* xbuf[NBUF] = { xb0, xb1, xb2 };

    const int tw0 = blockIdx.x * TILE_W;
    const int th0 = blockIdx.y * TILE_H;
    const int b   = blockIdx.z;
    const int tid = threadIdx.x;

    // --- Precompute float4 staging descriptors (12 slots/thread, reused 15x) ---
    int goff[12];
    #pragma unroll
    for (int s = 0; s < 12; ++s) {
        const int i = tid + NTHREADS * s;
        int o = -1;
        if (i < NSLOT4) {
            const int chan = i / 180;          // 180 float4 per channel plane
            const int p    = i - chan * 180;
            const int r    = p / 10;           // halo row 0..17
            const int g    = p - r * 10;       // 4-col group 0..9
            const int row  = th0 - 1 + r;
            const int col  = tw0 - 4 + 4 * g;  // group fully in or out (4 | tw0)
            if (row >= 0 && row < HH && col >= 0 && col < WWD)
                o = chan * HW + row * WWD + col;
        }
        goff[s] = o;
    }

    const float* xb = x + (size_t)b * CCH * HW;

    // --- Prologue: start chunk 0 and 1 copies, stage weights meanwhile ---
    stage_async(xbuf[0], xb, goff, tid);
    CP_COMMIT();
    stage_async(xbuf[1], xb + (size_t)CHUNK * HW, goff, tid);
    CP_COMMIT();

    // Weight split: wsA[(tap*64 + c)*8 + k] = W[k][c][tap] for k<8;
    //               wsB[c*12 + tap]        = W[8][c][tap]
    for (int i = tid; i < NTAP * CCH * NTAP; i += NTHREADS) {
        int k   = i / (CCH * NTAP);
        int rem = i - k * (CCH * NTAP);
        int c   = rem / NTAP;
        int tap = rem - c * NTAP;
        float v = Wt[(k * CCH + c) * NTAP + tap];
        if (k < 8) wsA[(tap * CCH + c) * 8 + k] = v;
        else       wsB[c * 12 + tap] = v;
    }

    const int w   = tid & 31;
    const int h4  = tid >> 5;            // 0..3 -> pixel rows 4*h4 .. 4*h4+3
    const int ghb = th0 + 4 * h4;        // first pixel's global row
    const int gw  = tw0 + w;

    // Packed accumulators per pixel p: acc[p][0..3] = k-pairs, acc8[p] = k=8
    u64t  acc[NPX][4];
    float acc8[NPX];
    #pragma unroll
    for (int p = 0; p < NPX; ++p) {
        #pragma unroll
        for (int j = 0; j < 4; ++j) acc[p][j] = pack2(bias[2 * j], bias[2 * j + 1]);
        acc8[p] = bias[8];
    }

    CP_WAIT1();           // chunk 0 resident; chunk 1 may still fly
    __syncthreads();      // + weights visible

    // ---------------- Conv via FFMA2: 9 logits for each of 4 stacked pixels ------
    for (int ch = 0; ch < NCHUNK; ++ch) {
        if (ch > 0) {
            if (ch < NCHUNK - 1) CP_WAIT1(); else CP_WAIT0();
            __syncthreads();
        }
        if (ch + 2 < NCHUNK) {   // stage 2 ahead into the buffer freed last iter
            stage_async(xbuf[(ch + 2) % NBUF], xb + (size_t)(ch + 2) * CHUNK * HW, goff, tid);
            CP_COMMIT();
        }

        const float* xsc = xbuf[ch % NBUF];
        #pragma unroll 2
        for (int c = 0; c < CHUNK; ++c) {
            const int cg = ch * CHUNK + c;

            // k=8 weights for all 9 taps: 3 LDS once per channel
            const float* w8p = wsB + cg * 12;
            const float4 w8lo = *reinterpret_cast<const float4*>(w8p);
            const float4 w8mi = *reinterpret_cast<const float4*>(w8p + 4);
            const float  w8hi = w8p[8];
            const float w8v[NTAP] = { w8lo.x, w8lo.y, w8lo.z, w8lo.w,
                                      w8mi.x, w8mi.y, w8mi.z, w8mi.w, w8hi };

            // union of the 4 pixels' 3x3 neighborhoods: 6 rows x 3 cols
            const float* xr = xsc + c * PLANE + (4 * h4) * ROWSPAN + (w + 3);
            float xv[6][3];
            #pragma unroll
            for (int r = 0; r < 6; ++r)
                #pragma unroll
                for (int j = 0; j < 3; ++j)
                    xv[r][j] = xr[r * ROWSPAN + j];

            #pragma unroll
            for (int di = 0; di < 3; ++di) {
                #pragma unroll
                for (int dj = 0; dj < 3; ++dj) {
                    const int tap = di * 3 + dj;
                    const float* wq = wsA + (tap * CCH + cg) * 8;
                    const ulonglong2 wp = *reinterpret_cast<const ulonglong2*>(wq);
                    const ulonglong2 wr = *reinterpret_cast<const ulonglong2*>(wq + 4);
                    const float w8t = w8v[tap];
                    #pragma unroll
                    for (int p = 0; p < NPX; ++p) {
                        const float a  = xv[p + di][dj];
                        const u64t  ad = dup2(a);
                        acc[p][0] = ffma2(ad, wp.x, acc[p][0]);
                        acc[p][1] = ffma2(ad, wp.y, acc[p][1]);
                        acc[p][2] = ffma2(ad, wr.x, acc[p][2]);
                        acc[p][3] = ffma2(ad, wr.y, acc[p][3]);
                        acc8[p]   = fmaf(a, w8t, acc8[p]);
                    }
                }
            }
        }
    }

    // ---------------- softmax * hamming per pixel (denominator cancels) ---------
    const float hamv[NTAP] = {0.0064f, 0.08f, 0.0064f,
                              0.08f,   1.0f,  0.08f,
                              0.0064f, 0.08f, 0.0064f};
    float mask[NPX][NTAP];
    #pragma unroll
    for (int p = 0; p < NPX; ++p) {
        float av[NTAP];
        #pragma unroll
        for (int j = 0; j < 4; ++j) {
            float2 f = *reinterpret_cast<float2*>(&acc[p][j]);
            av[2 * j] = f.x; av[2 * j + 1] = f.y;
        }
        av[8] = acc8[p];
        float mx = av[0];
        #pragma unroll
        for (int k = 1; k < NTAP; ++k) mx = fmaxf(mx, av[k]);
        float s = 0.f;
        #pragma unroll
        for (int k = 0; k < NTAP; ++k) {
            float e = __expf(av[k] - mx) * hamv[k];
            mask[p][k] = e;
            s += e;
        }
        const float inv = __fdividef(1.f, s);
        #pragma unroll
        for (int k = 0; k < NTAP; ++k) mask[p][k] *= inv;
    }

    // ---------------- reflect-padded offsets (union rows of the 4 pixels) -------
    int roff[6], coff[3];
    #pragma unroll
    for (int i = 0; i < 6; ++i) {
        int g = ghb - 1 + i;
        g = (g < 0) ? 1 : ((g >= HH) ? (HH - 2) : g);
        roff[i] = (g - th0 + 1) * ROWSPAN;
    }
    #pragma unroll
    for (int j = 0; j < 3; ++j) {
        int g = gw - 1 + j;
        g = (g < 0) ? 1 : ((g >= WWD) ? (WWD - 2) : g);
        coff[j] = g - tw0 + 4;
    }

    // ---------------- CARAFE lowpass + highpass residual ------------------------
    // At conv end buffers hold chunks 6(buf0), 7(buf1), 5(buf2) — all resident.
    // Reverse walk 7..0; chunk ch lives in buf[ch % 3]. Chunk 5-chr staged at
    // iter chr (chr=1..5) into the buffer freed by the previous iter's compute.
    float* outb = out + ((size_t)b * CCH) * HW + (size_t)ghb * WWD + gw;

    for (int chr = 0; chr < NCHUNK; ++chr) {
        const int ch = NCHUNK - 1 - chr;

        if (chr >= 3) {                 // consuming a staged chunk
            if (chr < NCHUNK - 1) CP_WAIT1(); else CP_WAIT0();
            __syncthreads();
        } else if (chr >= 1) {
            __syncthreads();            // buffer-reuse hazard for the stage below
        }

        if (chr >= 1 && chr <= 5) {     // stage chunk 5-chr into just-freed buffer
            const int cs = 5 - chr;
            stage_async(xbuf[cs % NBUF], xb + (size_t)cs * CHUNK * HW, goff, tid);
            CP_COMMIT();
        }

        const float* xsc = xbuf[ch % NBUF];
        #pragma unroll 2
        for (int c = 0; c < CHUNK; ++c) {
            const float* xc = xsc + c * PLANE;
            float v[6][3];
            #pragma unroll
            for (int i = 0; i < 6; ++i)
                #pragma unroll
                for (int j = 0; j < 3; ++j)
                    v[i][j] = xc[roff[i] + coff[j]];

            const size_t co = (size_t)(ch * CHUNK + c) * HW;
            #pragma unroll
            for (int p = 0; p < NPX; ++p) {
                // v[p+1][1] = pixel p's center (never reflected)
                float lp = mask[p][0] * v[p][0];
                #pragma unroll
                for (int k = 1; k < NTAP; ++k)
                    lp = fmaf(mask[p][k], v[p + k / 3][k % 3], lp);
                outb[co + (size_t)p * WWD] = 2.f * v[p + 1][1] - lp;
            }
        }
    }
}

extern "C" void kernel_launch(void* const* d_in, const int* in_sizes, int n_in,
                              void* d_out, int out_size)
{
    const float* x  = (const float*)d_in[0];
    const float* Wt = (const float*)d_in[1];
    const float* bs = (const float*)d_in[2];
    float* out = (float*)d_out;

    const int B = in_sizes[0] / (CCH * HW);

    cudaFuncSetAttribute(ahpf_fused_kernel,
                         cudaFuncAttributeMaxDynamicSharedMemorySize, SMEM_BYTES);

    dim3 grid(WWD / TILE_W, HH / TILE_H, B);
    ahpf_fused_kernel<<<grid, NTHREADS, SMEM_BYTES>>>(x, Wt, bs, out);
}

// round 14
// speedup vs baseline: 1.1107x; 1.1107x over previous
#include <cuda_runtime.h>
#include <cuda_bf16.h>
#include <cstdint>

#define TILE_H 16
#define TILE_W 32
#define HALO_H (TILE_H + 2)        // 18
#define ROWSPAN 40                 // padded row: gmem cols [tw0-4, tw0+36), 160B aligned
#define PLANE  (HALO_H * ROWSPAN)  // 720 floats per channel plane
#define CCH    64
#define HH     128
#define WWD    128
#define HW     (HH * WWD)
#define NTAP   9
#define CHUNK  8
#define NCHUNK (CCH / CHUNK)       // 8
#define NBUF   3
#define NPX    4                   // vertical pixels per conv thread
#define NPIX   (TILE_H * TILE_W)   // 512 pixels per CTA
#define NSLOT4 (CHUNK * HALO_H * 10)   // 1440 float4 slots per chunk staging

#define XS_ELEMS  (CHUNK * PLANE)      // 5760 floats per buffer
#define WSA_ELEMS (NTAP * CCH * 8)     // 4608: k=0..7 pairs, [tap][c][8]  (>= 9*512 scratch)
#define WSB_ELEMS (CCH * 12)           // 768:  k=8 weights, [c][tap] padded to 12
#define SMEM_BYTES ((NBUF * XS_ELEMS + WSA_ELEMS + WSB_ELEMS) * 4)  // 90624 B -> 2 CTA/SM

extern __shared__ float smem[];

typedef unsigned long long u64t;

#define CP_COMMIT() asm volatile("cp.async.commit_group;\n" ::: "memory")
#define CP_WAIT0()  asm volatile("cp.async.wait_group 0;\n" ::: "memory")
#define CP_WAIT1()  asm volatile("cp.async.wait_group 1;\n" ::: "memory")

__device__ __forceinline__ u64t pack2(float lo, float hi) {
    u64t r;
    asm("mov.b64 %0, {%1, %2};" : "=l"(r) : "r"(__float_as_uint(lo)), "r"(__float_as_uint(hi)));
    return r;
}
__device__ __forceinline__ u64t dup2(float v) {
    u64t r;
    asm("mov.b64 %0, {%1, %1};" : "=l"(r) : "r"(__float_as_uint(v)));
    return r;
}
// d = a*b + c elementwise on packed f32x2 -> single FFMA2 in SASS
__device__ __forceinline__ u64t ffma2(u64t a, u64t b, u64t c) {
    u64t d;
    asm("fma.rn.f32x2 %0, %1, %2, %3;" : "=l"(d) : "l"(a), "l"(b), "l"(c));
    return d;
}

// One 8-channel chunk = 1440 aligned float4 copies; 6 slots/thread, descriptors
// precomputed once. Invalid slots zero-fill via cp.async src-size=0, which also
// writes the conv's zero halo at image borders.
__device__ __forceinline__ void stage_async(float* __restrict__ buf,
                                            const float* __restrict__ xc,
                                            const int* __restrict__ goff,
                                            int tid)
{
    uint32_t sa = (uint32_t)__cvta_generic_to_shared(buf) + (uint32_t)tid * 16u;
    #pragma unroll
    for (int s = 0; s < 5; ++s) {
        const int o = goff[s];
        const float* src = xc + (o >= 0 ? o : 0);
        const int z = (o >= 0) ? 16 : 0;
        asm volatile("cp.async.cg.shared.global [%0], [%1], 16, %2;\n"
                     :: "r"(sa + (uint32_t)s * 4096u), "l"(src), "r"(z) : "memory");
    }
    if (tid < (NSLOT4 - 5 * 256)) {   // tid < 160
        const int o = goff[5];
        const float* src = xc + (o >= 0 ? o : 0);
        const int z = (o >= 0) ? 16 : 0;
        asm volatile("cp.async.cg.shared.global [%0], [%1], 16, %2;\n"
                     :: "r"(sa + 5u * 4096u), "l"(src), "r"(z) : "memory");
    }
}

__global__ __launch_bounds__(256, 2)
void ahpf_fused_kernel(const float* __restrict__ x,
                       const float* __restrict__ Wt,
                       const float* __restrict__ bias,
                       float* __restrict__ out)
{
    float* xb0 = smem;
    float* xb1 = smem + XS_ELEMS;
    float* xb2 = smem + 2 * XS_ELEMS;
    float* wsA = smem + NBUF * XS_ELEMS;            // [tap][c][8] : k=0..7; later: partial/mask [9][512]
    float* wsB = wsA + WSA_ELEMS;                   // [c][12]     : k=8 per tap
    float* xbuf[NBUF] = { xb0, xb1, xb2 };

    const int tw0 = blockIdx.x * TILE_W;
    const int th0 = blockIdx.y * TILE_H;
    const int b   = blockIdx.z;
    const int tid = threadIdx.x;

    // --- Precompute float4 staging descriptors (6 slots/thread, reused 15x) ---
    int goff[6];
    #pragma unroll
    for (int s = 0; s < 6; ++s) {
        const int i = tid + 256 * s;
        int o = -1;
        if (i < NSLOT4) {
            const int chan = i / 180;          // 180 float4 per channel plane
            const int p    = i - chan * 180;
            const int r    = p / 10;           // halo row 0..17
            const int g    = p - r * 10;       // 4-col group 0..9
            const int row  = th0 - 1 + r;
            const int col  = tw0 - 4 + 4 * g;  // group fully in or out (4 | tw0)
            if (row >= 0 && row < HH && col >= 0 && col < WWD)
                o = chan * HW + row * WWD + col;
        }
        goff[s] = o;
    }

    const float* xb = x + (size_t)b * CCH * HW;

    // --- Prologue: start chunk 0 and 1 copies, stage weights meanwhile ---
    stage_async(xbuf[0], xb, goff, tid);
    CP_COMMIT();
    stage_async(xbuf[1], xb + (size_t)CHUNK * HW, goff, tid);
    CP_COMMIT();

    // Weight split: wsA[(tap*64 + c)*8 + k] = W[k][c][tap] for k<8;
    //               wsB[c*12 + tap]        = W[8][c][tap]
    for (int i = tid; i < NTAP * CCH * NTAP; i += 256) {
        int k   = i / (CCH * NTAP);
        int rem = i - k * (CCH * NTAP);
        int c   = rem / NTAP;
        int tap = rem - c * NTAP;
        float v = Wt[(k * CCH + c) * NTAP + tap];
        if (k < 8) wsA[(tap * CCH + c) * 8 + k] = v;
        else       wsB[c * 12 + tap] = v;
    }

    // --- Conv thread mapping: 2 channel-groups x 128 px-threads x 4 vertical px ---
    const int group = tid >> 7;          // 0 or 1
    const int pt    = tid & 127;
    const int w     = pt & 31;
    const int h4    = pt >> 5;           // 0..3 -> pixel rows 4*h4 .. 4*h4+3
    const int pix0  = (4 * h4) * TILE_W + w;   // CTA-local pixel index of px p: pix0 + 32*p

    // Packed partial accumulators per pixel p; group 0 seeds bias, group 1 seeds 0.
    u64t  acc[NPX][4];
    float acc8[NPX];
    {
        u64t bp[4]; float b8;
        if (group == 0) {
            #pragma unroll
            for (int j = 0; j < 4; ++j) bp[j] = pack2(bias[2 * j], bias[2 * j + 1]);
            b8 = bias[8];
        } else {
            #pragma unroll
            for (int j = 0; j < 4; ++j) bp[j] = 0ull;
            b8 = 0.f;
        }
        #pragma unroll
        for (int p = 0; p < NPX; ++p) {
            #pragma unroll
            for (int j = 0; j < 4; ++j) acc[p][j] = bp[j];
            acc8[p] = b8;
        }
    }

    CP_WAIT1();           // chunk 0 resident; chunk 1 may still fly
    __syncthreads();      // + weights visible

    // ---------------- Conv via FFMA2: each group does 4 of 8 chunk channels ------
    for (int ch = 0; ch < NCHUNK; ++ch) {
        if (ch > 0) {
            if (ch < NCHUNK - 1) CP_WAIT1(); else CP_WAIT0();
            __syncthreads();
        }
        if (ch + 2 < NCHUNK) {   // stage 2 ahead into the buffer freed last iter
            stage_async(xbuf[(ch + 2) % NBUF], xb + (size_t)(ch + 2) * CHUNK * HW, goff, tid);
            CP_COMMIT();
        }

        const float* xsc = xbuf[ch % NBUF];
        #pragma unroll 2
        for (int c2 = 0; c2 < CHUNK / 2; ++c2) {
            const int c  = 2 * c2 + group;        // alternating channels per group
            const int cg = ch * CHUNK + c;

            // k=8 weights for all 9 taps: 3 LDS once per channel
            const float* w8p = wsB + cg * 12;
            const float4 w8lo = *reinterpret_cast<const float4*>(w8p);
            const float4 w8mi = *reinterpret_cast<const float4*>(w8p + 4);
            const float  w8hi = w8p[8];
            const float w8v[NTAP] = { w8lo.x, w8lo.y, w8lo.z, w8lo.w,
                                      w8mi.x, w8mi.y, w8mi.z, w8mi.w, w8hi };

            // union of the 4 pixels' 3x3 neighborhoods: 6 rows x 3 cols
            const float* xr = xsc + c * PLANE + (4 * h4) * ROWSPAN + (w + 3);
            float xv[6][3];
            #pragma unroll
            for (int r = 0; r < 6; ++r)
                #pragma unroll
                for (int j = 0; j < 3; ++j)
                    xv[r][j] = xr[r * ROWSPAN + j];

            #pragma unroll
            for (int di = 0; di < 3; ++di) {
                #pragma unroll
                for (int dj = 0; dj < 3; ++dj) {
                    const int tap = di * 3 + dj;
                    const float* wq = wsA + (tap * CCH + cg) * 8;
                    const ulonglong2 wp = *reinterpret_cast<const ulonglong2*>(wq);
                    const ulonglong2 wr = *reinterpret_cast<const ulonglong2*>(wq + 4);
                    const float w8t = w8v[tap];
                    #pragma unroll
                    for (int p = 0; p < NPX; ++p) {
                        const float a  = xv[p + di][dj];
                        const u64t  ad = dup2(a);
                        acc[p][0] = ffma2(ad, wp.x, acc[p][0]);
                        acc[p][1] = ffma2(ad, wp.y, acc[p][1]);
                        acc[p][2] = ffma2(ad, wr.x, acc[p][2]);
                        acc[p][3] = ffma2(ad, wr.y, acc[p][3]);
                        acc8[p]   = fmaf(a, w8t, acc8[p]);
                    }
                }
            }
        }
    }

    // ---------------- Cross-group reduction + softmax (wsA reused as [9][512]) ---
    __syncthreads();      // conv reads of wsA done; safe to overwrite
    if (group == 1) {     // publish partials: part[k][pix]
        #pragma unroll
        for (int p = 0; p < NPX; ++p) {
            const int px = pix0 + 32 * p;
            #pragma unroll
            for (int j = 0; j < 4; ++j) {
                float2 f = *reinterpret_cast<float2*>(&acc[p][j]);
                wsA[(2 * j)     * NPIX + px] = f.x;
                wsA[(2 * j + 1) * NPIX + px] = f.y;
            }
            wsA[8 * NPIX + px] = acc8[p];
        }
    }
    __syncthreads();
    if (group == 0) {     // combine, softmax*hamming (denominator cancels), publish masks
        const float hamv[NTAP] = {0.0064f, 0.08f, 0.0064f,
                                  0.08f,   1.0f,  0.08f,
                                  0.0064f, 0.08f, 0.0064f};
        #pragma unroll
        for (int p = 0; p < NPX; ++p) {
            const int px = pix0 + 32 * p;
            float av[NTAP];
            #pragma unroll
            for (int j = 0; j < 4; ++j) {
                float2 f = *reinterpret_cast<float2*>(&acc[p][j]);
                av[2 * j]     = f.x + wsA[(2 * j)     * NPIX + px];
                av[2 * j + 1] = f.y + wsA[(2 * j + 1) * NPIX + px];
            }
            av[8] = acc8[p] + wsA[8 * NPIX + px];

            float mx = av[0];
            #pragma unroll
            for (int k = 1; k < NTAP; ++k) mx = fmaxf(mx, av[k]);
            float s = 0.f;
            float e[NTAP];
            #pragma unroll
            for (int k = 0; k < NTAP; ++k) {
                e[k] = __expf(av[k] - mx) * hamv[k];
                s += e[k];
            }
            const float inv = __fdividef(1.f, s);
            #pragma unroll
            for (int k = 0; k < NTAP; ++k)
                wsA[k * NPIX + px] = e[k] * inv;   // overwrite own slots with masks
        }
    }
    __syncthreads();

    // ---------------- Carafe mapping: 2 vertical px per thread (all 256) ---------
    const int h2  = tid >> 5;            // 0..7 -> pixel rows 2*h2, 2*h2+1
    const int wc_ = tid & 31;
    const int gh0 = th0 + 2 * h2;
    const int gwc = tw0 + wc_;

    float mask0[NTAP], mask1[NTAP];
    {
        const int px0 = (2 * h2) * TILE_W + wc_;
        #pragma unroll
        for (int k = 0; k < NTAP; ++k) {
            mask0[k] = wsA[k * NPIX + px0];
            mask1[k] = wsA[k * NPIX + px0 + TILE_W];
        }
    }

    // reflect-padded offsets (shared by the pixel pair)
    int roff[4], coff[3];
    #pragma unroll
    for (int i = 0; i < 4; ++i) {
        int g = gh0 - 1 + i;
        g = (g < 0) ? 1 : ((g >= HH) ? (HH - 2) : g);
        roff[i] = (g - th0 + 1) * ROWSPAN;
    }
    #pragma unroll
    for (int j = 0; j < 3; ++j) {
        int g = gwc - 1 + j;
        g = (g < 0) ? 1 : ((g >= WWD) ? (WWD - 2) : g);
        coff[j] = g - tw0 + 4;
    }

    // ---------------- CARAFE lowpass + highpass residual ------------------------
    // At conv end the 3 buffers hold chunks 6(buf0), 7(buf1), 5(buf2) — all
    // resident. Reverse walk 7..0; chunk ch lives in buf[ch % 3]. Chunk 5-chr
    // staged at iter chr (chr=1..5) into the buffer freed by the previous iter.
    float* outb = out + ((size_t)b * CCH) * HW + (size_t)gh0 * WWD + gwc;

    for (int chr = 0; chr < NCHUNK; ++chr) {
        const int ch = NCHUNK - 1 - chr;

        if (chr >= 3) {                 // consuming a staged chunk
            if (chr < NCHUNK - 1) CP_WAIT1(); else CP_WAIT0();
            __syncthreads();
        } else if (chr >= 1) {
            __syncthreads();            // buffer-reuse hazard for the stage below
        }

        if (chr >= 1 && chr <= 5) {     // stage chunk 5-chr into just-freed buffer
            const int cs = 5 - chr;
            stage_async(xbuf[cs % NBUF], xb + (size_t)cs * CHUNK * HW, goff, tid);
            CP_COMMIT();
        }

        const float* xsc = xbuf[ch % NBUF];
        #pragma unroll 2
        for (int c = 0; c < CHUNK; ++c) {
            const float* xc = xsc + c * PLANE;
            float v[4][3];
            #pragma unroll
            for (int i = 0; i < 4; ++i)
                #pragma unroll
                for (int j = 0; j < 3; ++j)
                    v[i][j] = xc[roff[i] + coff[j]];

            // v[1][1] = center of pixel0, v[2][1] = center of pixel1 (never reflected)
            float lp0 = mask0[0] * v[0][0];
            float lp1 = mask1[0] * v[1][0];
            #pragma unroll
            for (int di = 0; di < 3; ++di)
                #pragma unroll
                for (int dj = 0; dj < 3; ++dj) {
                    if (di == 0 && dj == 0) continue;
                    lp0 = fmaf(mask0[di * 3 + dj], v[di][dj],     lp0);
                    lp1 = fmaf(mask1[di * 3 + dj], v[di + 1][dj], lp1);
                }

            const size_t co = (size_t)(ch * CHUNK + c) * HW;
            outb[co]       = 2.f * v[1][1] - lp0;
            outb[co + WWD] = 2.f * v[2][1] - lp1;
        }
    }
}

extern "C" void kernel_launch(void* const* d_in, const int* in_sizes, int n_in,
                              void* d_out, int out_size)
{
    const float* x  = (const float*)d_in[0];
    const float* Wt = (const float*)d_in[1];
    const float* bs = (const float*)d_in[2];
    float* out = (float*)d_out;

    const int B = in_sizes[0] / (CCH * HW);

    cudaFuncSetAttribute(ahpf_fused_kernel,
                         cudaFuncAttributeMaxDynamicSharedMemorySize, SMEM_BYTES);

    dim3 grid(WWD / TILE_W, HH / TILE_H, B);
    ahpf_fused_kernel<<<grid, 256, SMEM_BYTES>>>(x, Wt, bs, out);
}

// round 15
// speedup vs baseline: 1.1169x; 1.0056x over previous
#include <cuda_runtime.h>
#include <cuda_bf16.h>
#include <cstdint>

#define TILE_H 16
#define TILE_W 32
#define HALO_H (TILE_H + 2)        // 18
#define ROWSPAN 40                 // padded row: gmem cols [tw0-4, tw0+36), 160B aligned
#define PLANE  (HALO_H * ROWSPAN)  // 720 floats per channel plane
#define CCH    64
#define HH     128
#define WWD    128
#define HW     (HH * WWD)
#define NTAP   9
#define CHUNK  8
#define NCHUNK (CCH / CHUNK)       // 8
#define NBUF   3
#define NPX    4                   // vertical pixels per thread (both phases)
#define NPIX   (TILE_H * TILE_W)   // 512 pixels per CTA
#define NSLOT4 (CHUNK * HALO_H * 10)   // 1440 float4 slots per chunk staging

#define XS_ELEMS  (CHUNK * PLANE)      // 5760 floats per buffer
#define WSA_ELEMS (NTAP * CCH * 8)     // 4608: k=0..7 pairs, [tap][c][8] (== 9*512 scratch)
#define WSB_ELEMS (CCH * 12)           // 768:  k=8 weights, [c][tap] padded to 12
#define SMEM_BYTES ((NBUF * XS_ELEMS + WSA_ELEMS + WSB_ELEMS) * 4)  // 90624 B -> 2 CTA/SM

extern __shared__ float smem[];

typedef unsigned long long u64t;

#define CP_COMMIT() asm volatile("cp.async.commit_group;\n" ::: "memory")
#define CP_WAIT0()  asm volatile("cp.async.wait_group 0;\n" ::: "memory")
#define CP_WAIT1()  asm volatile("cp.async.wait_group 1;\n" ::: "memory")

__device__ __forceinline__ u64t pack2(float lo, float hi) {
    u64t r;
    asm("mov.b64 %0, {%1, %2};" : "=l"(r) : "r"(__float_as_uint(lo)), "r"(__float_as_uint(hi)));
    return r;
}
__device__ __forceinline__ u64t dup2(float v) {
    u64t r;
    asm("mov.b64 %0, {%1, %1};" : "=l"(r) : "r"(__float_as_uint(v)));
    return r;
}
// d = a*b + c elementwise on packed f32x2 -> single FFMA2 in SASS
__device__ __forceinline__ u64t ffma2(u64t a, u64t b, u64t c) {
    u64t d;
    asm("fma.rn.f32x2 %0, %1, %2, %3;" : "=l"(d) : "l"(a), "l"(b), "l"(c));
    return d;
}

// One 8-channel chunk = 1440 aligned float4 copies; 6 slots/thread, descriptors
// precomputed once. Invalid slots zero-fill via cp.async src-size=0, which also
// writes the conv's zero halo at image borders.
__device__ __forceinline__ void stage_async(float* __restrict__ buf,
                                            const float* __restrict__ xc,
                                            const int* __restrict__ goff,
                                            int tid)
{
    uint32_t sa = (uint32_t)__cvta_generic_to_shared(buf) + (uint32_t)tid * 16u;
    #pragma unroll
    for (int s = 0; s < 5; ++s) {
        const int o = goff[s];
        const float* src = xc + (o >= 0 ? o : 0);
        const int z = (o >= 0) ? 16 : 0;
        asm volatile("cp.async.cg.shared.global [%0], [%1], 16, %2;\n"
                     :: "r"(sa + (uint32_t)s * 4096u), "l"(src), "r"(z) : "memory");
    }
    if (tid < (NSLOT4 - 5 * 256)) {   // tid < 160
        const int o = goff[5];
        const float* src = xc + (o >= 0 ? o : 0);
        const int z = (o >= 0) ? 16 : 0;
        asm volatile("cp.async.cg.shared.global [%0], [%1], 16, %2;\n"
                     :: "r"(sa + 5u * 4096u), "l"(src), "r"(z) : "memory");
    }
}

__global__ __launch_bounds__(256, 2)
void ahpf_fused_kernel(const float* __restrict__ x,
                       const float* __restrict__ Wt,
                       const float* __restrict__ bias,
                       float* __restrict__ out)
{
    float* xb0 = smem;
    float* xb1 = smem + XS_ELEMS;
    float* xb2 = smem + 2 * XS_ELEMS;
    float* wsA = smem + NBUF * XS_ELEMS;            // [tap][c][8]; later: partials/masks [9][512]
    float* wsB = wsA + WSA_ELEMS;                   // [c][12] : k=8 per tap
    float* xbuf[NBUF] = { xb0, xb1, xb2 };

    const int tw0 = blockIdx.x * TILE_W;
    const int th0 = blockIdx.y * TILE_H;
    const int b   = blockIdx.z;
    const int tid = threadIdx.x;

    // --- Precompute float4 staging descriptors (6 slots/thread, reused 13x) ---
    int goff[6];
    #pragma unroll
    for (int s = 0; s < 6; ++s) {
        const int i = tid + 256 * s;
        int o = -1;
        if (i < NSLOT4) {
            const int chan = i / 180;          // 180 float4 per channel plane
            const int p    = i - chan * 180;
            const int r    = p / 10;           // halo row 0..17
            const int g    = p - r * 10;       // 4-col group 0..9
            const int row  = th0 - 1 + r;
            const int col  = tw0 - 4 + 4 * g;  // group fully in or out (4 | tw0)
            if (row >= 0 && row < HH && col >= 0 && col < WWD)
                o = chan * HW + row * WWD + col;
        }
        goff[s] = o;
    }

    const float* xb = x + (size_t)b * CCH * HW;

    // --- Prologue: start chunk 0 and 1 copies, stage weights meanwhile ---
    stage_async(xbuf[0], xb, goff, tid);
    CP_COMMIT();
    stage_async(xbuf[1], xb + (size_t)CHUNK * HW, goff, tid);
    CP_COMMIT();

    // Weight split: wsA[(tap*64 + c)*8 + k] = W[k][c][tap] for k<8;
    //               wsB[c*12 + tap]        = W[8][c][tap]
    for (int i = tid; i < NTAP * CCH * NTAP; i += 256) {
        int k   = i / (CCH * NTAP);
        int rem = i - k * (CCH * NTAP);
        int c   = rem / NTAP;
        int tap = rem - c * NTAP;
        float v = Wt[(k * CCH + c) * NTAP + tap];
        if (k < 8) wsA[(tap * CCH + c) * 8 + k] = v;
        else       wsB[c * 12 + tap] = v;
    }

    // --- Thread mapping (both phases): 2 channel-groups x 128 px-threads x 4 px ---
    const int group = tid >> 7;          // 0 or 1
    const int pt    = tid & 127;
    const int w     = pt & 31;
    const int h4    = pt >> 5;           // 0..3 -> pixel rows 4*h4 .. 4*h4+3
    const int pix0  = (4 * h4) * TILE_W + w;   // CTA-local pixel index of px p: pix0 + 32*p
    const int ghb   = th0 + 4 * h4;      // first pixel's global row
    const int gw    = tw0 + w;

    // Packed partial accumulators per pixel p; group 0 seeds bias, group 1 seeds 0.
    u64t  acc[NPX][4];
    float acc8[NPX];
    {
        u64t bp[4]; float b8;
        if (group == 0) {
            #pragma unroll
            for (int j = 0; j < 4; ++j) bp[j] = pack2(bias[2 * j], bias[2 * j + 1]);
            b8 = bias[8];
        } else {
            #pragma unroll
            for (int j = 0; j < 4; ++j) bp[j] = 0ull;
            b8 = 0.f;
        }
        #pragma unroll
        for (int p = 0; p < NPX; ++p) {
            #pragma unroll
            for (int j = 0; j < 4; ++j) acc[p][j] = bp[j];
            acc8[p] = b8;
        }
    }

    CP_WAIT1();           // chunk 0 resident; chunk 1 may still fly
    __syncthreads();      // + weights visible

    // ---------------- Conv via FFMA2: each group does 4 of 8 chunk channels ------
    for (int ch = 0; ch < NCHUNK; ++ch) {
        if (ch > 0) {
            if (ch < NCHUNK - 1) CP_WAIT1(); else CP_WAIT0();
            __syncthreads();
        }
        if (ch + 2 < NCHUNK) {   // stage 2 ahead into the buffer freed last iter
            stage_async(xbuf[(ch + 2) % NBUF], xb + (size_t)(ch + 2) * CHUNK * HW, goff, tid);
            CP_COMMIT();
        }

        const float* xsc = xbuf[ch % NBUF];
        #pragma unroll 2
        for (int c2 = 0; c2 < CHUNK / 2; ++c2) {
            const int c  = 2 * c2 + group;        // alternating channels per group
            const int cg = ch * CHUNK + c;

            // k=8 weights for all 9 taps: 3 LDS once per channel
            const float* w8p = wsB + cg * 12;
            const float4 w8lo = *reinterpret_cast<const float4*>(w8p);
            const float4 w8mi = *reinterpret_cast<const float4*>(w8p + 4);
            const float  w8hi = w8p[8];
            const float w8v[NTAP] = { w8lo.x, w8lo.y, w8lo.z, w8lo.w,
                                      w8mi.x, w8mi.y, w8mi.z, w8mi.w, w8hi };

            // union of the 4 pixels' 3x3 neighborhoods: 6 rows x 3 cols
            const float* xr = xsc + c * PLANE + (4 * h4) * ROWSPAN + (w + 3);
            float xv[6][3];
            #pragma unroll
            for (int r = 0; r < 6; ++r)
                #pragma unroll
                for (int j = 0; j < 3; ++j)
                    xv[r][j] = xr[r * ROWSPAN + j];

            #pragma unroll
            for (int di = 0; di < 3; ++di) {
                #pragma unroll
                for (int dj = 0; dj < 3; ++dj) {
                    const int tap = di * 3 + dj;
                    const float* wq = wsA + (tap * CCH + cg) * 8;
                    const ulonglong2 wp = *reinterpret_cast<const ulonglong2*>(wq);
                    const ulonglong2 wr = *reinterpret_cast<const ulonglong2*>(wq + 4);
                    const float w8t = w8v[tap];
                    #pragma unroll
                    for (int p = 0; p < NPX; ++p) {
                        const float a  = xv[p + di][dj];
                        const u64t  ad = dup2(a);
                        acc[p][0] = ffma2(ad, wp.x, acc[p][0]);
                        acc[p][1] = ffma2(ad, wp.y, acc[p][1]);
                        acc[p][2] = ffma2(ad, wr.x, acc[p][2]);
                        acc[p][3] = ffma2(ad, wr.y, acc[p][3]);
                        acc8[p]   = fmaf(a, w8t, acc8[p]);
                    }
                }
            }
        }
    }

    // ---------------- Cross-group reduction + softmax (wsA reused as [9][512]) ---
    __syncthreads();      // conv reads of wsA done; safe to overwrite
    if (group == 1) {     // publish partials: part[k][pix]
        #pragma unroll
        for (int p = 0; p < NPX; ++p) {
            const int px = pix0 + 32 * p;
            #pragma unroll
            for (int j = 0; j < 4; ++j) {
                float2 f = *reinterpret_cast<float2*>(&acc[p][j]);
                wsA[(2 * j)     * NPIX + px] = f.x;
                wsA[(2 * j + 1) * NPIX + px] = f.y;
            }
            wsA[8 * NPIX + px] = acc8[p];
        }
    }
    __syncthreads();
    if (group == 0) {     // combine, softmax*hamming (denominator cancels), publish masks
        const float hamv[NTAP] = {0.0064f, 0.08f, 0.0064f,
                                  0.08f,   1.0f,  0.08f,
                                  0.0064f, 0.08f, 0.0064f};
        #pragma unroll
        for (int p = 0; p < NPX; ++p) {
            const int px = pix0 + 32 * p;
            float av[NTAP];
            #pragma unroll
            for (int j = 0; j < 4; ++j) {
                float2 f = *reinterpret_cast<float2*>(&acc[p][j]);
                av[2 * j]     = f.x + wsA[(2 * j)     * NPIX + px];
                av[2 * j + 1] = f.y + wsA[(2 * j + 1) * NPIX + px];
            }
            av[8] = acc8[p] + wsA[8 * NPIX + px];

            float mx = av[0];
            #pragma unroll
            for (int k = 1; k < NTAP; ++k) mx = fmaxf(mx, av[k]);
            float s = 0.f;
            float e[NTAP];
            #pragma unroll
            for (int k = 0; k < NTAP; ++k) {
                e[k] = __expf(av[k] - mx) * hamv[k];
                s += e[k];
            }
            const float inv = __fdividef(1.f, s);
            #pragma unroll
            for (int k = 0; k < NTAP; ++k)
                wsA[k * NPIX + px] = e[k] * inv;   // overwrite own slots with masks
        }
    }
    __syncthreads();

    // ---------------- Carafe: same 4-px mapping, channels split across groups ----
    // Masks for this thread's 4 pixels (36 conflict-free LDS, amortized over 32 ch)
    float mask[NPX][NTAP];
    #pragma unroll
    for (int p = 0; p < NPX; ++p) {
        const int px = pix0 + 32 * p;
        #pragma unroll
        for (int k = 0; k < NTAP; ++k)
            mask[p][k] = wsA[k * NPIX + px];
    }

    // reflect-padded offsets (union rows of the 4 pixels)
    int roff[6], coff[3];
    #pragma unroll
    for (int i = 0; i < 6; ++i) {
        int g = ghb - 1 + i;
        g = (g < 0) ? 1 : ((g >= HH) ? (HH - 2) : g);
        roff[i] = (g - th0 + 1) * ROWSPAN;
    }
    #pragma unroll
    for (int j = 0; j < 3; ++j) {
        int g = gw - 1 + j;
        g = (g < 0) ? 1 : ((g >= WWD) ? (WWD - 2) : g);
        coff[j] = g - tw0 + 4;
    }

    // ---------------- CARAFE lowpass + highpass residual ------------------------
    // At conv end the 3 buffers hold chunks 6(buf0), 7(buf1), 5(buf2) — all
    // resident. Reverse walk 7..0; chunk ch lives in buf[ch % 3]. Chunk 5-chr
    // staged at iter chr (chr=1..5) into the buffer freed by the previous iter.
    float* outb = out + ((size_t)b * CCH) * HW + (size_t)ghb * WWD + gw;

    for (int chr = 0; chr < NCHUNK; ++chr) {
        const int ch = NCHUNK - 1 - chr;

        if (chr >= 3) {                 // consuming a staged chunk
            if (chr < NCHUNK - 1) CP_WAIT1(); else CP_WAIT0();
            __syncthreads();
        } else if (chr >= 1) {
            __syncthreads();            // buffer-reuse hazard for the stage below
        }

        if (chr >= 1 && chr <= 5) {     // stage chunk 5-chr into just-freed buffer
            const int cs = 5 - chr;
            stage_async(xbuf[cs % NBUF], xb + (size_t)cs * CHUNK * HW, goff, tid);
            CP_COMMIT();
        }

        const float* xsc = xbuf[ch % NBUF];
        #pragma unroll 2
        for (int c2 = 0; c2 < CHUNK / 2; ++c2) {
            const int c = 2 * c2 + group;          // alternating channels per group
            const float* xc = xsc + c * PLANE;
            float v[6][3];
            #pragma unroll
            for (int i = 0; i < 6; ++i)
                #pragma unroll
                for (int j = 0; j < 3; ++j)
                    v[i][j] = xc[roff[i] + coff[j]];

            const size_t co = (size_t)(ch * CHUNK + c) * HW;
            #pragma unroll
            for (int p = 0; p < NPX; ++p) {
                // v[p+1][1] = pixel p's center (never reflected)
                float lp = mask[p][0] * v[p][0];
                #pragma unroll
                for (int k = 1; k < NTAP; ++k)
                    lp = fmaf(mask[p][k], v[p + k / 3][k % 3], lp);
                outb[co + (size_t)p * WWD] = 2.f * v[p + 1][1] - lp;
            }
        }
    }
}

extern "C" void kernel_launch(void* const* d_in, const int* in_sizes, int n_in,
                              void* d_out, int out_size)
{
    const float* x  = (const float*)d_in[0];
    const float* Wt = (const float*)d_in[1];
    const float* bs = (const float*)d_in[2];
    float* out = (float*)d_out;

    const int B = in_sizes[0] / (CCH * HW);

    cudaFuncSetAttribute(ahpf_fused_kernel,
                         cudaFuncAttributeMaxDynamicSharedMemorySize, SMEM_BYTES);

    dim3 grid(WWD / TILE_W, HH / TILE_H, B);
    ahpf_fused_kernel<<<grid, 256, SMEM_BYTES>>>(x, Wt, bs, out);
}